// round 8
// baseline (speedup 1.0000x reference)
#include <cuda_runtime.h>
#include <cuda_fp16.h>
#include <cuda_bf16.h>
#include <math_constants.h>
#include <cstdint>

// ---------------- shapes ----------------
#define B_  256
#define T_  250
#define D_  700
#define H_  1024
#define O_  20
#define M_  (B_ * T_)   // 64000
#define KP_ 704         // K padded to multiple of 64

// ---------------- main GEMM tiling ----------------
#define BM 128
#define BN 64
#define BK 32
#define NCHUNK (KP_ / BK)              // 22
#define A_TILE_B (BM * BK * 2)         // 8192
#define W_TILE_B (BN * BK * 2)         // 4096
#define STAGE_B (2 * A_TILE_B + 2 * W_TILE_B)  // 24576
#define NSTAGE 4
#define SMEM_TOTAL (NSTAGE * STAGE_B)  // 98304 -> 2 CTAs/SM

#define A_SCALE 2048.0f
#define W_SCALE 64.0f
#define INV_SCALE (1.0f / (A_SCALE * W_SCALE))   // 2^-17, exact

// ---------------- phase-B (d2) GEMM tiling ----------------
#define PB_ROWS 256
#define PB_K    1024
#define PB_BK   64
#define PB_NCH  (PB_K / PB_BK)             // 16
#define PB_SPKBUF  (PB_ROWS * PB_BK * 2)   // 32768 per buffer
#define PB_W2TILE  (32 * PB_BK * 2)        // 4096 per split
#define PB_W2STAGE (2 * PB_W2TILE)         // 8192
#define PB_W2RING  4
#define PB_SMEM (2 * PB_SPKBUF + PB_W2RING * PB_W2STAGE)   // 98304

// ---------------- scratch (static device globals; no allocation) ----------------
__device__ float g_d1[(size_t)M_ * H_];
__device__ __half g_Ah[(size_t)M_ * KP_];
__device__ __half g_Al[(size_t)M_ * KP_];
__device__ __half g_Wh[(size_t)H_ * KP_];
__device__ __half g_Wl[(size_t)H_ * KP_];
__device__ uint32_t g_msk[(size_t)M_ * 32];            // spike bitmasks
__device__ __nv_bfloat16 g_W2s[2][32 * PB_K];          // W2 hi/lo bf16 splits (bit-permuted)
__device__ float g_d2[(size_t)M_ * 32];                // d2 (padded to 32 outputs)

// ---------------- family-safe PTX helpers ----------------
__device__ __forceinline__ uint32_t smem_to_u32(const void* smem_ptr) {
    uint32_t addr;
    asm("{ .reg .u64 tmp; cvta.to.shared.u64 tmp, %1; cvt.u32.u64 %0, tmp; }"
        : "=r"(addr) : "l"(smem_ptr));
    return addr;
}
#define CP_ASYNC16(dst_u32, src_ptr) \
    asm volatile("cp.async.cg.shared.global [%0], [%1], 16;" \
        :: "r"(dst_u32), "l"(src_ptr))
#define CP_COMMIT() asm volatile("cp.async.commit_group;" ::: "memory")
#define CP_WAIT2()  asm volatile("cp.async.wait_group 2;" ::: "memory")

__device__ __forceinline__ void ldsm_x4(uint32_t& r0, uint32_t& r1,
                                        uint32_t& r2, uint32_t& r3, uint32_t addr) {
    asm volatile("ldmatrix.sync.aligned.m8n8.x4.shared.b16 {%0,%1,%2,%3}, [%4];"
        : "=r"(r0), "=r"(r1), "=r"(r2), "=r"(r3) : "r"(addr));
}
__device__ __forceinline__ void mma16816_f16(float* c, const uint32_t* a, const uint32_t* b) {
    asm volatile(
        "mma.sync.aligned.m16n8k16.row.col.f32.f16.f16.f32 "
        "{%0,%1,%2,%3}, {%4,%5,%6,%7}, {%8,%9}, {%0,%1,%2,%3};"
        : "+f"(c[0]), "+f"(c[1]), "+f"(c[2]), "+f"(c[3])
        : "r"(a[0]), "r"(a[1]), "r"(a[2]), "r"(a[3]), "r"(b[0]), "r"(b[1]));
}
__device__ __forceinline__ void mma16816_bf16(float* c, const uint32_t* a, const uint32_t* b) {
    asm volatile(
        "mma.sync.aligned.m16n8k16.row.col.f32.bf16.bf16.f32 "
        "{%0,%1,%2,%3}, {%4,%5,%6,%7}, {%8,%9}, {%0,%1,%2,%3};"
        : "+f"(c[0]), "+f"(c[1]), "+f"(c[2]), "+f"(c[3])
        : "r"(a[0]), "r"(a[1]), "r"(a[2]), "r"(a[3]), "r"(b[0]), "r"(b[1]));
}
#define SWZ128(o) ((o) ^ (((o) >> 3) & 0x70))
// pair-packed address for 64-byte-row tiles (2 rows share a 128B line)
#define PK64(row, colbyte) ((uint32_t)((((row) >> 1) * 128) + (((row) & 1) * 64) + (colbyte)))

// expand 2 spike bits into packed bf16x2 (1.0f / 0.0f halves)
__device__ __forceinline__ uint32_t expand2(uint32_t b) {
    return ((b & 1u) * 0x3F80u) | ((b >> 1) * 0x3F800000u);
}

// ---------------------------------------------------------------------------
// Kernel 0: fp32 -> 2x fp16 split with pre-scale, 8 elems/thread.
// K padded 700 -> 704 with zeros.
// ---------------------------------------------------------------------------
__global__ void split2_kernel(const float* __restrict__ src, int rows, float scale,
                              __half* __restrict__ o0, __half* __restrict__ o1)
{
    const int GPR = KP_ / 8;  // 88
    long long idx = (long long)blockIdx.x * blockDim.x + threadIdx.x;
    if (idx >= (long long)rows * GPR) return;
    int m = (int)(idx / GPR);
    int g = (int)(idx % GPR);
    const float* sp = src + (size_t)m * D_ + g * 8;
    float4 f0 = *(const float4*)sp;                         // g*8 <= 696 < 700 always
    float4 f1 = (g < GPR - 1) ? *(const float4*)(sp + 4)
                              : make_float4(0.f, 0.f, 0.f, 0.f);
    float a[8] = {f0.x * scale, f0.y * scale, f0.z * scale, f0.w * scale,
                  f1.x * scale, f1.y * scale, f1.z * scale, f1.w * scale};
    unsigned short h0[8], h1[8];
#pragma unroll
    for (int i = 0; i < 8; i++) {
        __half hi = __float2half_rn(a[i]);
        __half lo = __float2half_rn(a[i] - __half2float(hi));
        h0[i] = __half_as_ushort(hi);
        h1[i] = __half_as_ushort(lo);
    }
    size_t off = (size_t)m * KP_ + g * 8;
    *(uint4*)(o0 + off) = make_uint4(
        (uint32_t)h0[1] << 16 | h0[0], (uint32_t)h0[3] << 16 | h0[2],
        (uint32_t)h0[5] << 16 | h0[4], (uint32_t)h0[7] << 16 | h0[6]);
    *(uint4*)(o1 + off) = make_uint4(
        (uint32_t)h1[1] << 16 | h1[0], (uint32_t)h1[3] << 16 | h1[2],
        (uint32_t)h1[5] << 16 | h1[4], (uint32_t)h1[7] << 16 | h1[6]);
}

// ---------------------------------------------------------------------------
// Kernel 0b: W2 -> 2x bf16 splits, PERMUTED to ballot bit order.
// h = (w>>2)*128 + l*4 + (w&3) for word w = p>>5, bit l = p&31.
// ---------------------------------------------------------------------------
__global__ void split_w2_kernel(const float* __restrict__ W2)
{
    int idx = blockIdx.x * blockDim.x + threadIdx.x;
    if (idx >= 32 * PB_K) return;
    int o = idx / PB_K;
    int p = idx % PB_K;
    int w = p >> 5, l = p & 31;
    int h = (w >> 2) * 128 + l * 4 + (w & 3);
    float v = (o < O_) ? W2[o * H_ + h] : 0.0f;
    __nv_bfloat16 hi = __float2bfloat16(v);
    __nv_bfloat16 lo = __float2bfloat16(v - __bfloat162float(hi));
    g_W2s[0][idx] = hi;
    g_W2s[1][idx] = lo;
}

// ---------------------------------------------------------------------------
// Kernel 1: HMMA fp16 GEMM, fp32 emulation via 3 cross-products.
// BM=128, BN=64, BK=32, 4-stage cp.async (prefetch distance 3), one
// __syncthreads per iteration, loads issued BEFORE the MMAs.
// 64B-row tiles with pair-packed SWZ128 layout. 2 CTAs/SM.
// ---------------------------------------------------------------------------
__global__ __launch_bounds__(256, 2)
void gemm_hmma_kernel(const float* __restrict__ bias)
{
    extern __shared__ __align__(1024) char smem[];
    const uint32_t smem_base = smem_to_u32(smem);
    const int tid  = threadIdx.x;
    const int wid  = tid >> 5;
    const int lane = tid & 31;
    const int wm = wid >> 1;       // 0..3 (m)
    const int wn = wid & 1;        // 0..1 (n)
    const int bm = blockIdx.y * BM;
    const int bn = blockIdx.x * BN;

    // cp.async geometry. A tile: 512 16B units, 2/thread. unit u: row=u>>2, cb=(u&3)*16.
    uint32_t sdstA[2];
    size_t   goffA[2];
#pragma unroll
    for (int j = 0; j < 2; j++) {
        int u = tid + j * 256;
        int row = u >> 2, cu = u & 3;
        sdstA[j] = SWZ128(PK64(row, cu * 16));
        goffA[j] = (size_t)row * KP_ + cu * 8;
    }
    // W tile: 256 units, 1/thread.
    const int wrowu = tid >> 2, wcu = tid & 3;
    const uint32_t sdstW = SWZ128(PK64(wrowu, wcu * 16));
    const size_t   goffW = (size_t)wrowu * KP_ + wcu * 8;

    const __half* Asrc[2] = { g_Ah + (size_t)bm * KP_, g_Al + (size_t)bm * KP_ };
    const __half* Wsrc[2] = { g_Wh + (size_t)bn * KP_, g_Wl + (size_t)bn * KP_ };

    // ldmatrix per-lane base addresses (pre-swizzle, colbyte part varies by kk)
    const int q  = lane >> 3;
    const int rr = lane & 7;
    uint32_t abase[2];             // A: mt 0..1
#pragma unroll
    for (int mt = 0; mt < 2; mt++) {
        int row = wm * 32 + mt * 16 + (q & 1) * 8 + rr;
        abase[mt] = PK64(row, (q >> 1) * 16);
    }
    uint32_t bbase[2];             // W: np 0..1
#pragma unroll
    for (int np = 0; np < 2; np++) {
        int row = wn * 32 + np * 16 + (q >> 1) * 8 + rr;
        bbase[np] = PK64(row, (q & 1) * 16);
    }

    float acc[2][4][4];
#pragma unroll
    for (int mt = 0; mt < 2; mt++)
#pragma unroll
        for (int nt = 0; nt < 4; nt++)
#pragma unroll
            for (int i = 0; i < 4; i++) acc[mt][nt][i] = 0.0f;

#define GEMM_LOAD_CHUNK(sb, k0) do { \
    _Pragma("unroll") \
    for (int s = 0; s < 2; s++) { \
        _Pragma("unroll") \
        for (int j = 0; j < 2; j++) \
            CP_ASYNC16((sb) + s * A_TILE_B + sdstA[j], Asrc[s] + goffA[j] + (k0)); \
        CP_ASYNC16((sb) + 2 * A_TILE_B + s * W_TILE_B + sdstW, Wsrc[s] + goffW + (k0)); \
    } \
} while (0)

    // prologue: chunks 0..2 into stages 0..2
#pragma unroll
    for (int pk = 0; pk < 3; pk++) {
        GEMM_LOAD_CHUNK(smem_base + pk * STAGE_B, pk * BK);
        CP_COMMIT();
    }

    const int pa[3] = {0, 0, 1};   // A split per term
    const int pb[3] = {0, 1, 0};   // W split per term

    for (int k = 0; k < NCHUNK; k++) {
        CP_WAIT2();                // chunk k resident (k+1, k+2 may be in flight)
        __syncthreads();           // chunk-k data visible; stage (k+3)&3 readers done

        if (k + 3 < NCHUNK)
            GEMM_LOAD_CHUNK(smem_base + ((k + 3) & 3) * STAGE_B, (k + 3) * BK);
        CP_COMMIT();               // always commit to keep group accounting aligned

        const uint32_t stage = smem_base + (k & 3) * STAGE_B;
#pragma unroll
        for (int kk = 0; kk < 2; kk++) {
            uint32_t af[2][2][4];   // [split][mt]
            uint32_t bf[2][4][2];   // [split][nt]
#pragma unroll
            for (int s = 0; s < 2; s++) {
#pragma unroll
                for (int mt = 0; mt < 2; mt++)
                    ldsm_x4(af[s][mt][0], af[s][mt][1], af[s][mt][2], af[s][mt][3],
                            stage + s * A_TILE_B + SWZ128(abase[mt] + kk * 32));
#pragma unroll
                for (int np = 0; np < 2; np++)
                    ldsm_x4(bf[s][np * 2][0], bf[s][np * 2][1],
                            bf[s][np * 2 + 1][0], bf[s][np * 2 + 1][1],
                            stage + 2 * A_TILE_B + s * W_TILE_B
                                  + SWZ128(bbase[np] + kk * 32));
            }
#pragma unroll
            for (int p = 0; p < 3; p++)
#pragma unroll
                for (int mt = 0; mt < 2; mt++)
#pragma unroll
                    for (int nt = 0; nt < 4; nt++)
                        mma16816_f16(acc[mt][nt], af[pa[p]][mt], bf[pb[p]][nt]);
        }
    }

    const int mrow0 = bm + wm * 32;
    const int ncol0 = bn + wn * 32;
    const int lr = lane >> 2;
    const int lc = (lane & 3) * 2;
#pragma unroll
    for (int mt = 0; mt < 2; mt++) {
#pragma unroll
        for (int nt = 0; nt < 4; nt++) {
            int r = mrow0 + mt * 16 + lr;
            int c = ncol0 + nt * 8 + lc;
            float bx = __ldg(bias + c), by = __ldg(bias + c + 1);
            float2 v0 = make_float2(acc[mt][nt][0] * INV_SCALE + bx,
                                    acc[mt][nt][1] * INV_SCALE + by);
            float2 v1 = make_float2(acc[mt][nt][2] * INV_SCALE + bx,
                                    acc[mt][nt][3] * INV_SCALE + by);
            *(float2*)(g_d1 + (size_t)r * H_ + c)       = v0;
            *(float2*)(g_d1 + (size_t)(r + 8) * H_ + c) = v1;
        }
    }
}

// ---------------------------------------------------------------------------
// Kernel 2a: LIF layer-1 chains -> spike BITMASKS via ballot. 512 CTAs x 128.
// word w = gwarp*4 + j holds at bit l the spike of h = gwarp*128 + l*4 + j.
// ---------------------------------------------------------------------------
__global__ __launch_bounds__(128) void lif1_kernel(
    const float* __restrict__ d1,
    const float* __restrict__ tau1)
{
    const int b    = blockIdx.x >> 1;
    const int half = blockIdx.x & 1;
    const int tid  = threadIdx.x;
    const int wl   = tid >> 5;
    const int lane = tid & 31;
    const int h0   = half * 512 + tid * 4;

    float4 tv = *(const float4*)(tau1 + h0);
    float a1[4], om[4], mem[4], spk[4];
    a1[0] = 1.0f / (1.0f + expf(-tv.x));
    a1[1] = 1.0f / (1.0f + expf(-tv.y));
    a1[2] = 1.0f / (1.0f + expf(-tv.z));
    a1[3] = 1.0f / (1.0f + expf(-tv.w));
#pragma unroll
    for (int j = 0; j < 4; j++) { om[j] = 1.0f - a1[j]; mem[j] = 0.0f; spk[j] = 0.0f; }

    const float* dp = d1 + (size_t)b * T_ * H_ + h0;
    uint32_t* mp = g_msk + (size_t)b * T_ * 32 + (half * 4 + wl) * 4;

    float4 nx0 = *(const float4*)dp;
    float4 nx1 = *(const float4*)(dp + H_);
    for (int t = 0; t < T_; t++) {
        float cur[4] = {nx0.x, nx0.y, nx0.z, nx0.w};
        nx0 = nx1;
        if (t + 2 < T_) nx1 = *(const float4*)(dp + (size_t)(t + 2) * H_);

#pragma unroll
        for (int j = 0; j < 4; j++) {
            mem[j] = mem[j] * a1[j] + om[j] * cur[j] - spk[j];
            spk[j] = (mem[j] > 1.0f) ? 1.0f : 0.0f;
        }
        uint32_t bits0 = __ballot_sync(0xffffffffu, mem[0] > 1.0f);
        uint32_t bits1 = __ballot_sync(0xffffffffu, mem[1] > 1.0f);
        uint32_t bits2 = __ballot_sync(0xffffffffu, mem[2] > 1.0f);
        uint32_t bits3 = __ballot_sync(0xffffffffu, mem[3] > 1.0f);
        if (lane < 4) {
            uint32_t w = (lane == 0) ? bits0 : (lane == 1) ? bits1
                       : (lane == 2) ? bits2 : bits3;
            mp[(size_t)t * 32 + lane] = w;
        }
    }
}

// ---------------------------------------------------------------------------
// Kernel 2b: d2^T = W2splits[32,1024] @ spk^T. Bitmask-expanded spikes.
// W2 in a 4-deep ring (race-free: writer >= 2 barriers after last reader).
// ---------------------------------------------------------------------------
__global__ __launch_bounds__(256, 2)
void d2_gemm_kernel()
{
    extern __shared__ __align__(1024) char smem[];
    const uint32_t smem_base = smem_to_u32(smem);
    const int tid  = threadIdx.x;
    const int wid  = tid >> 5;
    const int lane = tid & 31;
    const int m0 = blockIdx.x * PB_ROWS;

    // expansion geometry: idx = tid + i*256 -> row r = idx>>1, word wq = idx&1
    uint32_t ebase[2];
    const uint32_t* mrow[2];
#pragma unroll
    for (int i = 0; i < 2; i++) {
        int idx = tid + i * 256;
        int r = idx >> 1, wq = idx & 1;
        ebase[i] = (uint32_t)(r * 128 + wq * 64);
        mrow[i]  = g_msk + (size_t)(m0 + r) * 32 + wq;
    }

    // W2 cp.async geometry
    const int wrow = tid >> 3, wunit = tid & 7;
    const uint32_t w_sdst = SWZ128(wrow * 128 + wunit * 16);
    const size_t   w_goff = (size_t)wrow * PB_K + wunit * 8;
    const uint32_t w2smem = smem_base + 2 * PB_SPKBUF;

    // ldmatrix addresses
    const int q  = lane >> 3;
    const int rr = lane & 7;
    uint32_t abyte[2];
#pragma unroll
    for (int mt = 0; mt < 2; mt++) {
        int row = mt * 16 + (q & 1) * 8 + rr;
        abyte[mt] = (uint32_t)(row * 128 + (q >> 1) * 16);
    }
    uint32_t bbyte[2];
#pragma unroll
    for (int np = 0; np < 2; np++) {
        int row = wid * 32 + np * 16 + (q >> 1) * 8 + rr;
        bbyte[np] = (uint32_t)(row * 128 + (q & 1) * 16);
    }

    float acc[2][4][4];
#pragma unroll
    for (int mt = 0; mt < 2; mt++)
#pragma unroll
        for (int nt = 0; nt < 4; nt++)
#pragma unroll
            for (int i = 0; i < 4; i++) acc[mt][nt][i] = 0.0f;

    // prologue: W2 chunks 0,1 into ring slots 0,1
#pragma unroll
    for (int pk = 0; pk < 2; pk++) {
#pragma unroll
        for (int p = 0; p < 2; p++)
            CP_ASYNC16(w2smem + pk * PB_W2STAGE + p * PB_W2TILE + w_sdst,
                       &g_W2s[p][0] + w_goff + pk * PB_BK);
        CP_COMMIT();
    }
    uint32_t mcur[2];
#pragma unroll
    for (int i = 0; i < 2; i++) mcur[i] = mrow[i][0];

    for (int kc = 0; kc < PB_NCH; kc++) {
        __syncthreads();   // all warps past iter kc-1: spkbuf(kc&1) and ring slot free

        // prefetch W2 chunk kc+2 into ring slot (kc+2)&3 (last read at kc-2)
        if (kc + 2 < PB_NCH) {
#pragma unroll
            for (int p = 0; p < 2; p++)
                CP_ASYNC16(w2smem + ((kc + 2) & 3) * PB_W2STAGE + p * PB_W2TILE + w_sdst,
                           &g_W2s[p][0] + w_goff + (kc + 2) * PB_BK);
        }
        CP_COMMIT();       // always commit

        // expand masks -> spk bf16 tile
        char* sb = smem + (kc & 1) * PB_SPKBUF;
#pragma unroll
        for (int i = 0; i < 2; i++) {
            uint32_t W = mcur[i];
#pragma unroll
            for (int g = 0; g < 4; g++) {
                uint4 u;
                u.x = expand2((W >> (g * 8 + 0)) & 3u);
                u.y = expand2((W >> (g * 8 + 2)) & 3u);
                u.z = expand2((W >> (g * 8 + 4)) & 3u);
                u.w = expand2((W >> (g * 8 + 6)) & 3u);
                *(uint4*)(sb + SWZ128(ebase[i] + g * 16)) = u;
            }
        }
        CP_WAIT2();        // W2 chunk kc resident (kc+1, kc+2 in flight)
        __syncthreads();   // expansion + W2 visible to all warps

        const uint32_t spkb = smem_base + (kc & 1) * PB_SPKBUF;
        const uint32_t w2b  = w2smem + (kc & 3) * PB_W2STAGE;
#pragma unroll
        for (int kk = 0; kk < 4; kk++) {
            uint32_t bf[4][2];
#pragma unroll
            for (int np = 0; np < 2; np++)
                ldsm_x4(bf[np * 2][0], bf[np * 2][1], bf[np * 2 + 1][0], bf[np * 2 + 1][1],
                        spkb + SWZ128(bbyte[np] + kk * 32));
#pragma unroll
            for (int p = 0; p < 2; p++) {
                uint32_t af[2][4];
#pragma unroll
                for (int mt = 0; mt < 2; mt++)
                    ldsm_x4(af[mt][0], af[mt][1], af[mt][2], af[mt][3],
                            w2b + p * PB_W2TILE + SWZ128(abyte[mt] + kk * 32));
#pragma unroll
                for (int mt = 0; mt < 2; mt++)
#pragma unroll
                    for (int nt = 0; nt < 4; nt++)
                        mma16816_bf16(acc[mt][nt], af[mt], bf[nt]);
            }
        }

        if (kc + 1 < PB_NCH) {
#pragma unroll
            for (int i = 0; i < 2; i++) mcur[i] = mrow[i][(kc + 1) * 2];
        }
    }

#pragma unroll
    for (int mt = 0; mt < 2; mt++) {
#pragma unroll
        for (int nt = 0; nt < 4; nt++) {
            int o  = mt * 16 + (lane >> 2);
            int n  = wid * 32 + nt * 8 + (lane & 3) * 2;
            size_t gm = (size_t)(m0 + n);
            g_d2[gm * 32 + o]           = acc[mt][nt][0];
            g_d2[(gm + 1) * 32 + o]     = acc[mt][nt][1];
            g_d2[gm * 32 + o + 8]       = acc[mt][nt][2];
            g_d2[(gm + 1) * 32 + o + 8] = acc[mt][nt][3];
        }
    }
}

// ---------------------------------------------------------------------------
// Kernel 2c: readout EMA + softmax accumulate (max-free; |mem2|<<88 so safe).
// ---------------------------------------------------------------------------
__global__ __launch_bounds__(256) void readout_kernel(
    const float* __restrict__ tau2,
    const float* __restrict__ b2,
    float* __restrict__ out)
{
    const int warp = threadIdx.x >> 5;
    const int lane = threadIdx.x & 31;
    const int b = blockIdx.x * 8 + warp;

    float a2 = 0.0f, oma2 = 0.0f, bb = 0.0f, mem2 = 0.0f, accv = 0.0f;
    if (lane < O_) {
        a2 = 1.0f / (1.0f + expf(-tau2[lane]));
        oma2 = 1.0f - a2;
        bb = b2[lane];
    }

    const float* dp = g_d2 + (size_t)b * T_ * 32;
    float v = dp[lane];
    for (int t = 0; t < T_; t++) {
        float vn = (t + 1 < T_) ? dp[(size_t)(t + 1) * 32 + lane] : 0.0f;
        if (lane < O_) mem2 = mem2 * a2 + oma2 * (v + bb);
        float e = (lane < O_) ? expf(mem2) : 0.0f;
        float s = e;
#pragma unroll
        for (int off = 16; off > 0; off >>= 1)
            s += __shfl_xor_sync(0xffffffffu, s, off);
        if (t > 10 && lane < O_) accv += e / s;
        v = vn;
    }
    if (lane < O_) out[b * O_ + lane] = accv;
}

// ---------------------------------------------------------------------------
extern "C" void kernel_launch(void* const* d_in, const int* in_sizes, int n_in,
                              void* d_out, int out_size)
{
    const float* input = (const float*)d_in[0];  // [B,T,D]
    const float* W1    = (const float*)d_in[1];  // [H,D]
    const float* b1    = (const float*)d_in[2];  // [H]
    const float* tau1  = (const float*)d_in[3];  // [H]
    const float* W2    = (const float*)d_in[4];  // [O,H]
    const float* b2    = (const float*)d_in[5];  // [O]
    const float* tau2  = (const float*)d_in[6];  // [O]
    float* out = (float*)d_out;                  // [B,O]

    cudaFuncSetAttribute(gemm_hmma_kernel,
                         cudaFuncAttributeMaxDynamicSharedMemorySize, SMEM_TOTAL);
    cudaFuncSetAttribute(d2_gemm_kernel,
                         cudaFuncAttributeMaxDynamicSharedMemorySize, PB_SMEM);

    __half *ah, *al, *wh, *wl;
    float *d1p;
    cudaGetSymbolAddress((void**)&ah,  g_Ah);
    cudaGetSymbolAddress((void**)&al,  g_Al);
    cudaGetSymbolAddress((void**)&wh,  g_Wh);
    cudaGetSymbolAddress((void**)&wl,  g_Wl);
    cudaGetSymbolAddress((void**)&d1p, g_d1);

    {
        long long ng = (long long)M_ * (KP_ / 8);
        int blocks = (int)((ng + 255) / 256);
        split2_kernel<<<blocks, 256>>>(input, M_, A_SCALE, ah, al);
    }
    {
        long long ng = (long long)H_ * (KP_ / 8);
        int blocks = (int)((ng + 255) / 256);
        split2_kernel<<<blocks, 256>>>(W1, H_, W_SCALE, wh, wl);
    }
    split_w2_kernel<<<(32 * PB_K + 255) / 256, 256>>>(W2);

    dim3 ggrid(H_ / BN, M_ / BM);  // (16, 500)
    gemm_hmma_kernel<<<ggrid, 256, SMEM_TOTAL>>>(b1);

    lif1_kernel<<<2 * B_, 128>>>(d1p, tau1);
    d2_gemm_kernel<<<M_ / PB_ROWS, 256, PB_SMEM>>>();   // 250 CTAs
    readout_kernel<<<B_ / 8, 256>>>(tau2, b2, out);
}

// round 9
// speedup vs baseline: 1.0940x; 1.0940x over previous
#include <cuda_runtime.h>
#include <cuda_fp16.h>
#include <cuda_bf16.h>
#include <math_constants.h>
#include <cstdint>

// ---------------- shapes ----------------
#define B_  256
#define T_  250
#define D_  700
#define H_  1024
#define O_  20
#define M_  (B_ * T_)   // 64000
#define KP_ 704         // K padded to multiple of 64

// ---------------- main GEMM tiling (R7-proven config) ----------------
#define BM 128
#define BN 64
#define BK 64
#define NCHUNK (KP_ / BK)              // 11
#define A_TILE_B (BM * BK * 2)         // 16384
#define W_TILE_B (BN * BK * 2)         // 8192
#define STAGE_B (2 * A_TILE_B + 2 * W_TILE_B)  // 49152
#define NSTAGE 2
#define SMEM_TOTAL (NSTAGE * STAGE_B)  // 98304 -> 2 CTAs/SM

#define A_SCALE 2048.0f
#define W_SCALE 64.0f
#define INV_SCALE (1.0f / (A_SCALE * W_SCALE))   // 2^-17, exact

// ---------------- phase-B (d2) GEMM tiling ----------------
#define PB_ROWS 256
#define PB_K    1024
#define PB_BK   64
#define PB_NCH  (PB_K / PB_BK)             // 16
#define PB_SPKBUF  (PB_ROWS * PB_BK * 2)   // 32768 per buffer
#define PB_W2TILE  (32 * PB_BK * 2)        // 4096 per split
#define PB_W2STAGE (2 * PB_W2TILE)         // 8192
#define PB_W2RING  4
#define PB_SMEM (2 * PB_SPKBUF + PB_W2RING * PB_W2STAGE)   // 98304

// ---------------- scratch (static device globals; no allocation) ----------------
__device__ float g_d1[(size_t)M_ * H_];
__device__ __half g_Ah[(size_t)M_ * KP_];
__device__ __half g_Al[(size_t)M_ * KP_];
__device__ __half g_Wh[(size_t)H_ * KP_];
__device__ __half g_Wl[(size_t)H_ * KP_];
__device__ uint32_t g_msk[(size_t)M_ * 32];            // spike bitmasks
__device__ __nv_bfloat16 g_W2s[2][32 * PB_K];          // W2 hi/lo bf16 splits (bit-permuted)
__device__ float g_d2[(size_t)M_ * 32];                // d2 (padded to 32 outputs)

// ---------------- family-safe PTX helpers ----------------
__device__ __forceinline__ uint32_t smem_to_u32(const void* smem_ptr) {
    uint32_t addr;
    asm("{ .reg .u64 tmp; cvta.to.shared.u64 tmp, %1; cvt.u32.u64 %0, tmp; }"
        : "=r"(addr) : "l"(smem_ptr));
    return addr;
}
#define CP_ASYNC16(dst_u32, src_ptr) \
    asm volatile("cp.async.cg.shared.global [%0], [%1], 16;" \
        :: "r"(dst_u32), "l"(src_ptr))
#define CP_COMMIT() asm volatile("cp.async.commit_group;" ::: "memory")
#define CP_WAIT1()  asm volatile("cp.async.wait_group 1;" ::: "memory")
#define CP_WAIT2()  asm volatile("cp.async.wait_group 2;" ::: "memory")

__device__ __forceinline__ void ldsm_x4(uint32_t& r0, uint32_t& r1,
                                        uint32_t& r2, uint32_t& r3, uint32_t addr) {
    asm volatile("ldmatrix.sync.aligned.m8n8.x4.shared.b16 {%0,%1,%2,%3}, [%4];"
        : "=r"(r0), "=r"(r1), "=r"(r2), "=r"(r3) : "r"(addr));
}
__device__ __forceinline__ void mma16816_f16(float* c, const uint32_t* a, const uint32_t* b) {
    asm volatile(
        "mma.sync.aligned.m16n8k16.row.col.f32.f16.f16.f32 "
        "{%0,%1,%2,%3}, {%4,%5,%6,%7}, {%8,%9}, {%0,%1,%2,%3};"
        : "+f"(c[0]), "+f"(c[1]), "+f"(c[2]), "+f"(c[3])
        : "r"(a[0]), "r"(a[1]), "r"(a[2]), "r"(a[3]), "r"(b[0]), "r"(b[1]));
}
__device__ __forceinline__ void mma16816_bf16(float* c, const uint32_t* a, const uint32_t* b) {
    asm volatile(
        "mma.sync.aligned.m16n8k16.row.col.f32.bf16.bf16.f32 "
        "{%0,%1,%2,%3}, {%4,%5,%6,%7}, {%8,%9}, {%0,%1,%2,%3};"
        : "+f"(c[0]), "+f"(c[1]), "+f"(c[2]), "+f"(c[3])
        : "r"(a[0]), "r"(a[1]), "r"(a[2]), "r"(a[3]), "r"(b[0]), "r"(b[1]));
}
#define SWZ128(o) ((o) ^ (((o) >> 3) & 0x70))

// expand 2 spike bits into packed bf16x2 (1.0f / 0.0f halves)
__device__ __forceinline__ uint32_t expand2(uint32_t b) {
    return ((b & 1u) * 0x3F80u) | ((b >> 1) * 0x3F800000u);
}

// ---------------------------------------------------------------------------
// Kernel 0: fp32 -> 2x fp16 split with pre-scale, 8 elems/thread.
// K padded 700 -> 704 with zeros.
// ---------------------------------------------------------------------------
__global__ void split2_kernel(const float* __restrict__ src, int rows, float scale,
                              __half* __restrict__ o0, __half* __restrict__ o1)
{
    const int GPR = KP_ / 8;  // 88
    long long idx = (long long)blockIdx.x * blockDim.x + threadIdx.x;
    if (idx >= (long long)rows * GPR) return;
    int m = (int)(idx / GPR);
    int g = (int)(idx % GPR);
    const float* sp = src + (size_t)m * D_ + g * 8;
    float4 f0 = *(const float4*)sp;                         // g*8 <= 696 < 700 always
    float4 f1 = (g < GPR - 1) ? *(const float4*)(sp + 4)
                              : make_float4(0.f, 0.f, 0.f, 0.f);
    float a[8] = {f0.x * scale, f0.y * scale, f0.z * scale, f0.w * scale,
                  f1.x * scale, f1.y * scale, f1.z * scale, f1.w * scale};
    unsigned short h0[8], h1[8];
#pragma unroll
    for (int i = 0; i < 8; i++) {
        __half hi = __float2half_rn(a[i]);
        __half lo = __float2half_rn(a[i] - __half2float(hi));
        h0[i] = __half_as_ushort(hi);
        h1[i] = __half_as_ushort(lo);
    }
    size_t off = (size_t)m * KP_ + g * 8;
    *(uint4*)(o0 + off) = make_uint4(
        (uint32_t)h0[1] << 16 | h0[0], (uint32_t)h0[3] << 16 | h0[2],
        (uint32_t)h0[5] << 16 | h0[4], (uint32_t)h0[7] << 16 | h0[6]);
    *(uint4*)(o1 + off) = make_uint4(
        (uint32_t)h1[1] << 16 | h1[0], (uint32_t)h1[3] << 16 | h1[2],
        (uint32_t)h1[5] << 16 | h1[4], (uint32_t)h1[7] << 16 | h1[6]);
}

// ---------------------------------------------------------------------------
// Kernel 0b: W2 -> 2x bf16 splits, PERMUTED to ballot bit order.
// h = (w>>2)*128 + l*4 + (w&3) for word w = p>>5, bit l = p&31.
// ---------------------------------------------------------------------------
__global__ void split_w2_kernel(const float* __restrict__ W2)
{
    int idx = blockIdx.x * blockDim.x + threadIdx.x;
    if (idx >= 32 * PB_K) return;
    int o = idx / PB_K;
    int p = idx % PB_K;
    int w = p >> 5, l = p & 31;
    int h = (w >> 2) * 128 + l * 4 + (w & 3);
    float v = (o < O_) ? W2[o * H_ + h] : 0.0f;
    __nv_bfloat16 hi = __float2bfloat16(v);
    __nv_bfloat16 lo = __float2bfloat16(v - __bfloat162float(hi));
    g_W2s[0][idx] = hi;
    g_W2s[1][idx] = lo;
}

// ---------------------------------------------------------------------------
// Kernel 1: HMMA fp16 GEMM, fp32 emulation via 3 cross-products.
// R7-proven: BM=128, BN=64, BK=64, 2-stage cp.async, 96KB smem -> 2 CTAs/SM.
// 8 warps in 4(m) x 2(n); warp tile 32x32.
// ---------------------------------------------------------------------------
__global__ __launch_bounds__(256, 2)
void gemm_hmma_kernel(const float* __restrict__ bias)
{
    extern __shared__ __align__(1024) char smem[];
    const uint32_t smem_base = smem_to_u32(smem);
    const int tid  = threadIdx.x;
    const int wid  = tid >> 5;
    const int lane = tid & 31;
    const int wm = wid >> 1;       // 0..3 (m)
    const int wn = wid & 1;        // 0..1 (n)
    const int bm = blockIdx.y * BM;
    const int bn = blockIdx.x * BN;

    // cp.async geometry. A tile (128 rows x 128B): 1024 chunks, 4/thread.
    uint32_t sdstA[4];
    size_t   goffA[4];
#pragma unroll
    for (int j = 0; j < 4; j++) {
        int c = tid + j * 256;
        int row = c >> 3, unit = c & 7;
        sdstA[j] = SWZ128(row * 128 + unit * 16);
        goffA[j] = (size_t)row * KP_ + unit * 8;
    }
    // W tile (64 rows x 128B): 512 chunks, 2/thread.
    uint32_t sdstW[2];
    size_t   goffW[2];
#pragma unroll
    for (int j = 0; j < 2; j++) {
        int c = tid + j * 256;
        int row = c >> 3, unit = c & 7;
        sdstW[j] = SWZ128(row * 128 + unit * 16);
        goffW[j] = (size_t)row * KP_ + unit * 8;
    }
    const __half* Asrc[2] = { g_Ah + (size_t)bm * KP_, g_Al + (size_t)bm * KP_ };
    const __half* Wsrc[2] = { g_Wh + (size_t)bn * KP_, g_Wl + (size_t)bn * KP_ };

    // ldmatrix per-lane addresses
    const int q  = lane >> 3;
    const int rr = lane & 7;
    uint32_t abyte[2];             // A: mt 0..1, 16 rows each
#pragma unroll
    for (int mt = 0; mt < 2; mt++) {
        int row = wm * 32 + mt * 16 + (q & 1) * 8 + rr;
        abyte[mt] = (uint32_t)(row * 128 + (q >> 1) * 16);
    }
    uint32_t bbyte[2];             // W: np 0..1, 16 rows each (-> nt pairs)
#pragma unroll
    for (int np = 0; np < 2; np++) {
        int row = wn * 32 + np * 16 + (q >> 1) * 8 + rr;
        bbyte[np] = (uint32_t)(row * 128 + (q & 1) * 16);
    }

    float acc[2][4][4];
#pragma unroll
    for (int mt = 0; mt < 2; mt++)
#pragma unroll
        for (int nt = 0; nt < 4; nt++)
#pragma unroll
            for (int i = 0; i < 4; i++) acc[mt][nt][i] = 0.0f;

#define GEMM_LOAD_CHUNK(sb, k0) do { \
    _Pragma("unroll") \
    for (int s = 0; s < 2; s++) { \
        _Pragma("unroll") \
        for (int j = 0; j < 4; j++) \
            CP_ASYNC16((sb) + s * A_TILE_B + sdstA[j], Asrc[s] + goffA[j] + (k0)); \
        _Pragma("unroll") \
        for (int j = 0; j < 2; j++) \
            CP_ASYNC16((sb) + 2 * A_TILE_B + s * W_TILE_B + sdstW[j], \
                       Wsrc[s] + goffW[j] + (k0)); \
    } \
} while (0)

    // prologue: stages 0,1
    GEMM_LOAD_CHUNK(smem_base, 0);
    CP_COMMIT();
    GEMM_LOAD_CHUNK(smem_base + STAGE_B, BK);
    CP_COMMIT();

    const int pa[3] = {0, 0, 1};
    const int pb[3] = {0, 1, 0};

    for (int k = 0; k < NCHUNK; k++) {
        CP_WAIT1();
        __syncthreads();

        const uint32_t stage = smem_base + (k & 1) * STAGE_B;
#pragma unroll
        for (int kk = 0; kk < 4; kk++) {
            uint32_t af[2][2][4];   // [split][mt]
            uint32_t bf[2][4][2];   // [split][nt]
#pragma unroll
            for (int s = 0; s < 2; s++) {
#pragma unroll
                for (int mt = 0; mt < 2; mt++)
                    ldsm_x4(af[s][mt][0], af[s][mt][1], af[s][mt][2], af[s][mt][3],
                            stage + s * A_TILE_B + SWZ128(abyte[mt] + kk * 32));
#pragma unroll
                for (int np = 0; np < 2; np++)
                    ldsm_x4(bf[s][np * 2][0], bf[s][np * 2][1],
                            bf[s][np * 2 + 1][0], bf[s][np * 2 + 1][1],
                            stage + 2 * A_TILE_B + s * W_TILE_B
                                  + SWZ128(bbyte[np] + kk * 32));
            }
#pragma unroll
            for (int p = 0; p < 3; p++)
#pragma unroll
                for (int mt = 0; mt < 2; mt++)
#pragma unroll
                    for (int nt = 0; nt < 4; nt++)
                        mma16816_f16(acc[mt][nt], af[pa[p]][mt], bf[pb[p]][nt]);
        }
        __syncthreads();

        if (k + NSTAGE < NCHUNK) {
            GEMM_LOAD_CHUNK(smem_base + (k & 1) * STAGE_B, (k + NSTAGE) * BK);
        }
        CP_COMMIT();
    }

    const int mrow0 = bm + wm * 32;
    const int ncol0 = bn + wn * 32;
    const int lr = lane >> 2;
    const int lc = (lane & 3) * 2;
#pragma unroll
    for (int mt = 0; mt < 2; mt++) {
#pragma unroll
        for (int nt = 0; nt < 4; nt++) {
            int r = mrow0 + mt * 16 + lr;
            int c = ncol0 + nt * 8 + lc;
            float bx = __ldg(bias + c), by = __ldg(bias + c + 1);
            float2 v0 = make_float2(acc[mt][nt][0] * INV_SCALE + bx,
                                    acc[mt][nt][1] * INV_SCALE + by);
            float2 v1 = make_float2(acc[mt][nt][2] * INV_SCALE + bx,
                                    acc[mt][nt][3] * INV_SCALE + by);
            *(float2*)(g_d1 + (size_t)r * H_ + c)       = v0;
            *(float2*)(g_d1 + (size_t)(r + 8) * H_ + c) = v1;
        }
    }
}

// ---------------------------------------------------------------------------
// Kernel 2a: LIF layer-1 chains -> spike BITMASKS via ballot. 512 CTAs x 128.
// word w = gwarp*4 + j holds at bit l the spike of h = gwarp*128 + l*4 + j.
// ---------------------------------------------------------------------------
__global__ __launch_bounds__(128) void lif1_kernel(
    const float* __restrict__ d1,
    const float* __restrict__ tau1)
{
    const int b    = blockIdx.x >> 1;
    const int half = blockIdx.x & 1;
    const int tid  = threadIdx.x;
    const int wl   = tid >> 5;
    const int lane = tid & 31;
    const int h0   = half * 512 + tid * 4;

    float4 tv = *(const float4*)(tau1 + h0);
    float a1[4], om[4], mem[4], spk[4];
    a1[0] = 1.0f / (1.0f + expf(-tv.x));
    a1[1] = 1.0f / (1.0f + expf(-tv.y));
    a1[2] = 1.0f / (1.0f + expf(-tv.z));
    a1[3] = 1.0f / (1.0f + expf(-tv.w));
#pragma unroll
    for (int j = 0; j < 4; j++) { om[j] = 1.0f - a1[j]; mem[j] = 0.0f; spk[j] = 0.0f; }

    const float* dp = d1 + (size_t)b * T_ * H_ + h0;
    uint32_t* mp = g_msk + (size_t)b * T_ * 32 + (half * 4 + wl) * 4;

    float4 nx0 = *(const float4*)dp;
    float4 nx1 = *(const float4*)(dp + H_);
    for (int t = 0; t < T_; t++) {
        float cur[4] = {nx0.x, nx0.y, nx0.z, nx0.w};
        nx0 = nx1;
        if (t + 2 < T_) nx1 = *(const float4*)(dp + (size_t)(t + 2) * H_);

#pragma unroll
        for (int j = 0; j < 4; j++) {
            mem[j] = mem[j] * a1[j] + om[j] * cur[j] - spk[j];
            spk[j] = (mem[j] > 1.0f) ? 1.0f : 0.0f;
        }
        uint32_t bits0 = __ballot_sync(0xffffffffu, mem[0] > 1.0f);
        uint32_t bits1 = __ballot_sync(0xffffffffu, mem[1] > 1.0f);
        uint32_t bits2 = __ballot_sync(0xffffffffu, mem[2] > 1.0f);
        uint32_t bits3 = __ballot_sync(0xffffffffu, mem[3] > 1.0f);
        if (lane < 4) {
            uint32_t w = (lane == 0) ? bits0 : (lane == 1) ? bits1
                       : (lane == 2) ? bits2 : bits3;
            mp[(size_t)t * 32 + lane] = w;
        }
    }
}

// ---------------------------------------------------------------------------
// Kernel 2b: d2^T = W2splits[32,1024] @ spk^T. Bitmask-expanded spikes.
// W2 in a 4-deep ring (race-free: writer >= 2 barriers after last reader).
// ---------------------------------------------------------------------------
__global__ __launch_bounds__(256, 2)
void d2_gemm_kernel()
{
    extern __shared__ __align__(1024) char smem[];
    const uint32_t smem_base = smem_to_u32(smem);
    const int tid  = threadIdx.x;
    const int wid  = tid >> 5;
    const int lane = tid & 31;
    const int m0 = blockIdx.x * PB_ROWS;

    // expansion geometry: idx = tid + i*256 -> row r = idx>>1, word wq = idx&1
    uint32_t ebase[2];
    const uint32_t* mrow[2];
#pragma unroll
    for (int i = 0; i < 2; i++) {
        int idx = tid + i * 256;
        int r = idx >> 1, wq = idx & 1;
        ebase[i] = (uint32_t)(r * 128 + wq * 64);
        mrow[i]  = g_msk + (size_t)(m0 + r) * 32 + wq;
    }

    // W2 cp.async geometry
    const int wrow = tid >> 3, wunit = tid & 7;
    const uint32_t w_sdst = SWZ128(wrow * 128 + wunit * 16);
    const size_t   w_goff = (size_t)wrow * PB_K + wunit * 8;
    const uint32_t w2smem = smem_base + 2 * PB_SPKBUF;

    // ldmatrix addresses
    const int q  = lane >> 3;
    const int rr = lane & 7;
    uint32_t abyte[2];
#pragma unroll
    for (int mt = 0; mt < 2; mt++) {
        int row = mt * 16 + (q & 1) * 8 + rr;
        abyte[mt] = (uint32_t)(row * 128 + (q >> 1) * 16);
    }
    uint32_t bbyte[2];
#pragma unroll
    for (int np = 0; np < 2; np++) {
        int row = wid * 32 + np * 16 + (q >> 1) * 8 + rr;
        bbyte[np] = (uint32_t)(row * 128 + (q & 1) * 16);
    }

    float acc[2][4][4];
#pragma unroll
    for (int mt = 0; mt < 2; mt++)
#pragma unroll
        for (int nt = 0; nt < 4; nt++)
#pragma unroll
            for (int i = 0; i < 4; i++) acc[mt][nt][i] = 0.0f;

    // prologue: W2 chunks 0,1 into ring slots 0,1
#pragma unroll
    for (int pk = 0; pk < 2; pk++) {
#pragma unroll
        for (int p = 0; p < 2; p++)
            CP_ASYNC16(w2smem + pk * PB_W2STAGE + p * PB_W2TILE + w_sdst,
                       &g_W2s[p][0] + w_goff + pk * PB_BK);
        CP_COMMIT();
    }
    uint32_t mcur[2];
#pragma unroll
    for (int i = 0; i < 2; i++) mcur[i] = mrow[i][0];

    for (int kc = 0; kc < PB_NCH; kc++) {
        __syncthreads();   // all warps past iter kc-1: spkbuf(kc&1) and ring slot free

        // prefetch W2 chunk kc+2 into ring slot (kc+2)&3 (last read at kc-2)
        if (kc + 2 < PB_NCH) {
#pragma unroll
            for (int p = 0; p < 2; p++)
                CP_ASYNC16(w2smem + ((kc + 2) & 3) * PB_W2STAGE + p * PB_W2TILE + w_sdst,
                           &g_W2s[p][0] + w_goff + (kc + 2) * PB_BK);
        }
        CP_COMMIT();       // always commit

        // expand masks -> spk bf16 tile
        char* sb = smem + (kc & 1) * PB_SPKBUF;
#pragma unroll
        for (int i = 0; i < 2; i++) {
            uint32_t W = mcur[i];
#pragma unroll
            for (int g = 0; g < 4; g++) {
                uint4 u;
                u.x = expand2((W >> (g * 8 + 0)) & 3u);
                u.y = expand2((W >> (g * 8 + 2)) & 3u);
                u.z = expand2((W >> (g * 8 + 4)) & 3u);
                u.w = expand2((W >> (g * 8 + 6)) & 3u);
                *(uint4*)(sb + SWZ128(ebase[i] + g * 16)) = u;
            }
        }
        CP_WAIT2();        // W2 chunk kc resident (kc+1, kc+2 in flight)
        __syncthreads();   // expansion + W2 visible to all warps

        const uint32_t spkb = smem_base + (kc & 1) * PB_SPKBUF;
        const uint32_t w2b  = w2smem + (kc & 3) * PB_W2STAGE;
#pragma unroll
        for (int kk = 0; kk < 4; kk++) {
            uint32_t bf[4][2];
#pragma unroll
            for (int np = 0; np < 2; np++)
                ldsm_x4(bf[np * 2][0], bf[np * 2][1], bf[np * 2 + 1][0], bf[np * 2 + 1][1],
                        spkb + SWZ128(bbyte[np] + kk * 32));
#pragma unroll
            for (int p = 0; p < 2; p++) {
                uint32_t af[2][4];
#pragma unroll
                for (int mt = 0; mt < 2; mt++)
                    ldsm_x4(af[mt][0], af[mt][1], af[mt][2], af[mt][3],
                            w2b + p * PB_W2TILE + SWZ128(abyte[mt] + kk * 32));
#pragma unroll
                for (int mt = 0; mt < 2; mt++)
#pragma unroll
                    for (int nt = 0; nt < 4; nt++)
                        mma16816_bf16(acc[mt][nt], af[mt], bf[nt]);
            }
        }

        if (kc + 1 < PB_NCH) {
#pragma unroll
            for (int i = 0; i < 2; i++) mcur[i] = mrow[i][(kc + 1) * 2];
        }
    }

#pragma unroll
    for (int mt = 0; mt < 2; mt++) {
#pragma unroll
        for (int nt = 0; nt < 4; nt++) {
            int o  = mt * 16 + (lane >> 2);
            int n  = wid * 32 + nt * 8 + (lane & 3) * 2;
            size_t gm = (size_t)(m0 + n);
            g_d2[gm * 32 + o]           = acc[mt][nt][0];
            g_d2[(gm + 1) * 32 + o]     = acc[mt][nt][1];
            g_d2[gm * 32 + o + 8]       = acc[mt][nt][2];
            g_d2[(gm + 1) * 32 + o + 8] = acc[mt][nt][3];
        }
    }
}

// ---------------------------------------------------------------------------
// Kernel 2c: readout EMA + softmax accumulate (max-free; |mem2|<<88 so safe).
// ---------------------------------------------------------------------------
__global__ __launch_bounds__(256) void readout_kernel(
    const float* __restrict__ tau2,
    const float* __restrict__ b2,
    float* __restrict__ out)
{
    const int warp = threadIdx.x >> 5;
    const int lane = threadIdx.x & 31;
    const int b = blockIdx.x * 8 + warp;

    float a2 = 0.0f, oma2 = 0.0f, bb = 0.0f, mem2 = 0.0f, accv = 0.0f;
    if (lane < O_) {
        a2 = 1.0f / (1.0f + expf(-tau2[lane]));
        oma2 = 1.0f - a2;
        bb = b2[lane];
    }

    const float* dp = g_d2 + (size_t)b * T_ * 32;
    float v = dp[lane];
    for (int t = 0; t < T_; t++) {
        float vn = (t + 1 < T_) ? dp[(size_t)(t + 1) * 32 + lane] : 0.0f;
        if (lane < O_) mem2 = mem2 * a2 + oma2 * (v + bb);
        float e = (lane < O_) ? expf(mem2) : 0.0f;
        float s = e;
#pragma unroll
        for (int off = 16; off > 0; off >>= 1)
            s += __shfl_xor_sync(0xffffffffu, s, off);
        if (t > 10 && lane < O_) accv += e / s;
        v = vn;
    }
    if (lane < O_) out[b * O_ + lane] = accv;
}

// ---------------------------------------------------------------------------
extern "C" void kernel_launch(void* const* d_in, const int* in_sizes, int n_in,
                              void* d_out, int out_size)
{
    const float* input = (const float*)d_in[0];  // [B,T,D]
    const float* W1    = (const float*)d_in[1];  // [H,D]
    const float* b1    = (const float*)d_in[2];  // [H]
    const float* tau1  = (const float*)d_in[3];  // [H]
    const float* W2    = (const float*)d_in[4];  // [O,H]
    const float* b2    = (const float*)d_in[5];  // [O]
    const float* tau2  = (const float*)d_in[6];  // [O]
    float* out = (float*)d_out;                  // [B,O]

    cudaFuncSetAttribute(gemm_hmma_kernel,
                         cudaFuncAttributeMaxDynamicSharedMemorySize, SMEM_TOTAL);
    cudaFuncSetAttribute(d2_gemm_kernel,
                         cudaFuncAttributeMaxDynamicSharedMemorySize, PB_SMEM);

    __half *ah, *al, *wh, *wl;
    float *d1p;
    cudaGetSymbolAddress((void**)&ah,  g_Ah);
    cudaGetSymbolAddress((void**)&al,  g_Al);
    cudaGetSymbolAddress((void**)&wh,  g_Wh);
    cudaGetSymbolAddress((void**)&wl,  g_Wl);
    cudaGetSymbolAddress((void**)&d1p, g_d1);

    {
        long long ng = (long long)M_ * (KP_ / 8);
        int blocks = (int)((ng + 255) / 256);
        split2_kernel<<<blocks, 256>>>(input, M_, A_SCALE, ah, al);
    }
    {
        long long ng = (long long)H_ * (KP_ / 8);
        int blocks = (int)((ng + 255) / 256);
        split2_kernel<<<blocks, 256>>>(W1, H_, W_SCALE, wh, wl);
    }
    split_w2_kernel<<<(32 * PB_K + 255) / 256, 256>>>(W2);

    dim3 ggrid(H_ / BN, M_ / BM);  // (16, 500)
    gemm_hmma_kernel<<<ggrid, 256, SMEM_TOTAL>>>(b1);

    lif1_kernel<<<2 * B_, 128>>>(d1p, tau1);
    d2_gemm_kernel<<<M_ / PB_ROWS, 256, PB_SMEM>>>();   // 250 CTAs
    readout_kernel<<<B_ / 8, 256>>>(tau2, b2, out);
}